// round 2
// baseline (speedup 1.0000x reference)
#include <cuda_runtime.h>
#include <cuda_bf16.h>

#define B_DIM     32
#define N_ORDER   64
#define N_SPEC    4096
#define N_REST    200000
#define N_LATENT  6

// scratch: decoded rest-frame line spectra, layout [b][r]
__device__ float g_xlines[B_DIM * N_REST];

// ---------------------------------------------------------------------------
// Pass 1: x_lines[b][r] = sin( dot(s[b,:], W[r,:]) + bias[r] )
// One thread per r; loops over all 32 samples. s cached in shared memory.
// ---------------------------------------------------------------------------
__global__ void decode_kernel(const float* __restrict__ s,
                              const float* __restrict__ W,
                              const float* __restrict__ bias)
{
    __shared__ float sh_s[B_DIM * N_LATENT];
    int tid = threadIdx.x;
    if (tid < B_DIM * N_LATENT) sh_s[tid] = s[tid];
    __syncthreads();

    int r = blockIdx.x * blockDim.x + tid;
    if (r >= N_REST) return;

    float w[N_LATENT];
#pragma unroll
    for (int l = 0; l < N_LATENT; ++l) w[l] = W[r * N_LATENT + l];
    float bb = bias[r];

#pragma unroll 4
    for (int b = 0; b < B_DIM; ++b) {
        float acc = bb;
#pragma unroll
        for (int l = 0; l < N_LATENT; ++l)
            acc = fmaf(sh_s[b * N_LATENT + l], w[l], acc);
        g_xlines[b * N_REST + r] = sinf(acc);
    }
}

// ---------------------------------------------------------------------------
// Pass 2: Catmull-Rom interpolation at redshifted wavelengths.
// out[b][o][si] = 1 - interp(wave_rest, x_lines[b], wave_obs[o][si]*(1-z[b][o]))
// ---------------------------------------------------------------------------
__global__ void interp_kernel(const float* __restrict__ z,
                              const float* __restrict__ wave_rest,
                              const float* __restrict__ wave_obs,
                              float* __restrict__ out)
{
    int idx = blockIdx.x * blockDim.x + threadIdx.x;   // total fits in int (8.39M)
    const int total = B_DIM * N_ORDER * N_SPEC;
    if (idx >= total) return;

    int si = idx & (N_SPEC - 1);
    int bo = idx >> 12;            // /N_SPEC
    int o  = bo & (N_ORDER - 1);
    int b  = bo >> 6;

    float xq = wave_obs[o * N_SPEC + si] * (1.0f - __ldg(&z[b * N_ORDER + o]));

    // analytic guess for the searchsorted cell on the uniform grid
    const float w0       = 3800.0f;
    const float inv_step = 199999.0f / 3200.0f;
    int k = (int)((xq - w0) * inv_step);
    if (k < 0) k = 0;
    if (k > N_REST - 2) k = N_REST - 2;
    // fixup to exactly match searchsorted(..., 'right')-1 on the real fp32 knots
    while (k + 1 < N_REST && __ldg(&wave_rest[k + 1]) <= xq) ++k;
    while (k > 0 && __ldg(&wave_rest[k]) > xq) --k;
    // clip(1, N-3)
    if (k < 1) k = 1;
    if (k > N_REST - 3) k = N_REST - 3;

    float xm1 = __ldg(&wave_rest[k - 1]);
    float x0  = __ldg(&wave_rest[k]);
    float x1  = __ldg(&wave_rest[k + 1]);
    float x2  = __ldg(&wave_rest[k + 2]);

    const float* yb = g_xlines + b * N_REST;
    float ym1 = __ldg(&yb[k - 1]);
    float y0  = __ldg(&yb[k]);
    float y1  = __ldg(&yb[k + 1]);
    float y2  = __ldg(&yb[k + 2]);

    float h  = x1 - x0;
    float t  = __fdividef(xq - x0, h);
    float t2 = t * t;
    float t3 = t2 * t;
    float h00 = 2.0f * t3 - 3.0f * t2 + 1.0f;
    float h10 = t3 - 2.0f * t2 + t;
    float h01 = -2.0f * t3 + 3.0f * t2;
    float h11 = t3 - t2;
    float m0 = __fdividef(y1 - ym1, x1 - xm1) * h;
    float m1 = __fdividef(y2 - y0, x2 - x0) * h;

    float val = h00 * y0 + h10 * m0 + h01 * y1 + h11 * m1;
    out[idx] = 1.0f - val;
}

extern "C" void kernel_launch(void* const* d_in, const int* in_sizes, int n_in,
                              void* d_out, int out_size)
{
    const float* s         = (const float*)d_in[0];   // [32, 6]
    const float* z         = (const float*)d_in[1];   // [32, 64]
    const float* W         = (const float*)d_in[2];   // [200000, 6]
    const float* bias      = (const float*)d_in[3];   // [200000]
    const float* wave_rest = (const float*)d_in[4];   // [200000]
    const float* wave_obs  = (const float*)d_in[5];   // [64, 4096]
    float* out             = (float*)d_out;           // [32, 64, 4096]

    {
        int threads = 256;
        int blocks  = (N_REST + threads - 1) / threads;
        decode_kernel<<<blocks, threads>>>(s, W, bias);
    }
    {
        int total   = B_DIM * N_ORDER * N_SPEC;
        int threads = 512;
        int blocks  = (total + threads - 1) / threads;
        interp_kernel<<<blocks, threads>>>(z, wave_rest, wave_obs, out);
    }
}

// round 12
// speedup vs baseline: 1.2469x; 1.2469x over previous
#include <cuda_runtime.h>
#include <cuda_bf16.h>

#define B_DIM     32
#define N_ORDER   64
#define N_SPEC    4096
#define N_REST    200000
#define N_LATENT  6
#define WINDOW    3200      // knots per (b,o) window: ~3140 needed + margin
#define ITHREADS  512

// ---------------------------------------------------------------------------
// Fused kernel: one block per (b, o).
//  Stage 1: for the ~3131-knot window this order touches, compute
//           y[r] = sin(dot(s[b], W[r]) + bias[r]) and store (wave_rest[r], y)
//           interleaved in shared memory.
//  Stage 2: Catmull-Rom interpolate all 4096 redshifted queries from smem.
// ---------------------------------------------------------------------------
__global__ __launch_bounds__(ITHREADS, 4)
void telluric_kernel(const float* __restrict__ s,
                     const float* __restrict__ z,
                     const float* __restrict__ W,
                     const float* __restrict__ bias,
                     const float* __restrict__ wave_rest,
                     const float* __restrict__ wave_obs,
                     float* __restrict__ out)
{
    __shared__ float2 sw[WINDOW];   // (.x = wave_rest knot, .y = decoded y)

    const int bo  = blockIdx.x;                // b*N_ORDER + o
    const int o   = bo & (N_ORDER - 1);
    const int b   = bo >> 6;
    const int tid = threadIdx.x;

    const float scale = 1.0f - __ldg(&z[bo]);

    const float w0       = 3800.0f;
    const float inv_step = 199999.0f / 3200.0f;

    // window start: a few knots below the first query's cell
    const float xq_first = __ldg(&wave_obs[o * N_SPEC]) * scale;
    int w_lo = (int)((xq_first - w0) * inv_step) - 8;
    if (w_lo < 0) w_lo = 0;
    if (w_lo > N_REST - WINDOW) w_lo = N_REST - WINDOW;

    // latent vector for this b (6 floats, in registers)
    float sv[N_LATENT];
#pragma unroll
    for (int l = 0; l < N_LATENT; ++l) sv[l] = __ldg(&s[b * N_LATENT + l]);

    // Stage 1: decode + stage window (coalesced W/bias/wave_rest reads)
    for (int j = tid; j < WINDOW; j += ITHREADS) {
        int r = w_lo + j;
        float acc = __ldg(&bias[r]);
        const float* wr = W + r * N_LATENT;
#pragma unroll
        for (int l = 0; l < N_LATENT; ++l)
            acc = fmaf(sv[l], __ldg(&wr[l]), acc);
        sw[j] = make_float2(__ldg(&wave_rest[r]), sinf(acc));
    }
    __syncthreads();

    // Stage 2: interpolate
    const float* wo_row = wave_obs + o * N_SPEC;
    float* out_row = out + bo * N_SPEC;

#pragma unroll 2
    for (int si = tid; si < N_SPEC; si += ITHREADS) {
        float xq = __ldg(&wo_row[si]) * scale;

        // analytic guess (window-local), then exact fixup vs fp32 knots
        int k = (int)((xq - w0) * inv_step) - w_lo;
        if (k < 1) k = 1;
        if (k > WINDOW - 3) k = WINDOW - 3;
        while (k < WINDOW - 3 && sw[k + 1].x <= xq) ++k;
        while (k > 1 && sw[k].x > xq) --k;

        float2 pm1 = sw[k - 1];
        float2 p0  = sw[k];
        float2 p1  = sw[k + 1];
        float2 p2  = sw[k + 2];

        float h  = p1.x - p0.x;
        float t  = __fdividef(xq - p0.x, h);
        float t2 = t * t;
        float t3 = t2 * t;
        float h00 = 2.0f * t3 - 3.0f * t2 + 1.0f;
        float h10 = t3 - 2.0f * t2 + t;
        float h01 = -2.0f * t3 + 3.0f * t2;
        float h11 = t3 - t2;
        float m0 = __fdividef(p1.y - pm1.y, p1.x - pm1.x) * h;
        float m1 = __fdividef(p2.y - p0.y,  p2.x - p0.x)  * h;

        float val = h00 * p0.y + h10 * m0 + h01 * p1.y + h11 * m1;
        out_row[si] = 1.0f - val;
    }
}

extern "C" void kernel_launch(void* const* d_in, const int* in_sizes, int n_in,
                              void* d_out, int out_size)
{
    const float* s         = (const float*)d_in[0];   // [32, 6]
    const float* z         = (const float*)d_in[1];   // [32, 64]
    const float* W         = (const float*)d_in[2];   // [200000, 6]
    const float* bias      = (const float*)d_in[3];   // [200000]
    const float* wave_rest = (const float*)d_in[4];   // [200000]
    const float* wave_obs  = (const float*)d_in[5];   // [64, 4096]
    float* out             = (float*)d_out;           // [32, 64, 4096]

    int blocks = B_DIM * N_ORDER;                     // one block per (b, o)
    telluric_kernel<<<blocks, ITHREADS>>>(s, z, W, bias, wave_rest, wave_obs, out);
}